// round 9
// baseline (speedup 1.0000x reference)
#include <cuda_runtime.h>

typedef unsigned long long u64;

#define BATCH    8192
#define COLS     16          // columns per block
#define NTHREADS 512         // 16 warps; warp = 2 chunks x 16 cols
#define NBLOCKS  (BATCH / COLS)

// Packed coefficient tables, written by prep_kernel in exactly the layout the
// hot loops read (warp-uniform, consecutive 16B entries):
//  g_tabN[nl*256 + chunk*8 + e] : normal layers, {(c_lo,c_hi),(s_lo,s_hi)}
//  g_tabS[sl*512 + chunk*16 + k]: swap layers,   {(c,c),(s,-s)}
__device__ ulonglong2 g_tabN[16 * 256];
__device__ ulonglong2 g_tabS[4 * 512];

__global__ void prep_kernel(const float* __restrict__ ang) {
    int t = blockIdx.x * blockDim.x + threadIdx.x;
    if (t < 16 * 256) {
        const int nl = t >> 8, E = t & 255;
        const int p = nl >> 3, posn = nl & 7;
        const int w = E >> 3, e = E & 7;
        int l, plo, phi;
        if (posn < 4) { l = p * 10 + posn;           plo = 16 * w + e; phi = plo + 8;   }
        else          { l = p * 10 + 5 + (posn - 4); plo = 32 * e + w; phi = plo + 256; }
        float c0, s0, c1, s1;
        sincosf(ang[l * 512 + plo], &s0, &c0);
        sincosf(ang[l * 512 + phi], &s1, &c1);
        u64 cc, ss;
        asm("mov.b64 %0, {%1, %2};" : "=l"(cc) : "f"(c0), "f"(c1));
        asm("mov.b64 %0, {%1, %2};" : "=l"(ss) : "f"(s0), "f"(s1));
        g_tabN[t] = make_ulonglong2(cc, ss);
    } else if (t < 16 * 256 + 4 * 512) {
        const int t2 = t - 4096;
        const int sl = t2 >> 9, r = t2 & 511;
        const int w = r >> 4, k = r & 15;
        const int p = sl >> 1, isB = sl & 1;
        const int l = p * 10 + (isB ? 9 : 4);
        const int pp = isB ? (w + 32 * k) : (16 * w + k);
        float c, s;
        sincosf(ang[l * 512 + pp], &s, &c);
        u64 cc, sn;
        asm("mov.b64 %0, {%1, %1};" : "=l"(cc) : "f"(c));
        float ns = -s;
        asm("mov.b64 %0, {%1, %2};" : "=l"(sn) : "f"(s), "f"(ns));
        g_tabS[t2] = make_ulonglong2(cc, sn);
    }
}

// ---- packed f32x2 helpers ----
__device__ __forceinline__ u64 pk(float lo, float hi) {
    u64 r; asm("mov.b64 %0, {%1, %2};" : "=l"(r) : "f"(lo), "f"(hi)); return r;
}
__device__ __forceinline__ void up(u64 x, float& lo, float& hi) {
    asm("mov.b64 {%0, %1}, %2;" : "=f"(lo), "=f"(hi) : "l"(x));
}
__device__ __forceinline__ u64 swap2(u64 x) {
    u64 r;
    asm("{ .reg .b32 a, b; mov.b64 {a, b}, %1; mov.b64 %0, {b, a}; }"
        : "=l"(r) : "l"(x));
    return r;
}
__device__ __forceinline__ u64 mul2(u64 a, u64 b) {
    u64 d; asm("mul.rn.f32x2 %0, %1, %2;" : "=l"(d) : "l"(a), "l"(b)); return d;
}
__device__ __forceinline__ u64 fma2(u64 a, u64 b, u64 c) {
    u64 d; asm("fma.rn.f32x2 %0, %1, %2, %3;" : "=l"(d) : "l"(a), "l"(b), "l"(c)); return d;
}

// Normal layer, register-stride 2^SH: 8 rotations on u64 pairs (k, k+2^SH),
// coefs warp-uniform at t[e] (consecutive 16B entries).
template<int SH>
__device__ __forceinline__ void lnorm(u64* Xp, const ulonglong2* __restrict__ t) {
#pragma unroll
    for (int e = 0; e < 8; ++e) {
        const int s = 1 << SH;
        const int k = ((e >> SH) << (SH + 1)) | (e & (s - 1));
        const ulonglong2 cs = __ldg(t + e);
        const u64 nss = cs.y ^ 0x8000000080000000ULL;
        const u64 x0 = Xp[k], x1 = Xp[k + s];
        Xp[k]     = fma2(cs.x, x0, mul2(cs.y, x1));
        Xp[k + s] = fma2(cs.x, x1, mul2(nss,  x0));
    }
}

// Swap layer: each u64's halves are a pair. y = (s,-s)*swap(x) + (c,c)*x.
__device__ __forceinline__ void lswap(u64* Xp, const ulonglong2* __restrict__ t) {
#pragma unroll
    for (int k = 0; k < 16; ++k) {
        const ulonglong2 cs = __ldg(t + k);
        Xp[k] = fma2(cs.y, swap2(Xp[k]), mul2(cs.x, Xp[k]));
    }
}

// Smem tile [1024][16] floats (64 KB), swizzled: bit4 of the word address is
// XORed with row bit5, making bank bit4 = row0^row5 -> both exchange patterns
// (2 rows x 16 cols, halves differing in row bit5 or row bit0) are 1-phase
// conflict-free. Bijective (row recoverable from high bits).
__device__ __forceinline__ int tadr(int row, int c) {
    return ((row << 4) | c) ^ (((row >> 5) & 1) << 4);
}

extern "C" __global__ void __launch_bounds__(NTHREADS, 2)
butterfly_kernel(const float* __restrict__ X, float* __restrict__ Y)
{
    extern __shared__ float tile[];        // 1024*16 floats = 64 KB

    const int tid   = threadIdx.x;
    const int lane  = tid & 31;
    const int w0    = tid >> 5;            // warp 0..15
    const int h     = (lane >> 4) & 1;     // half-warp
    const int c16   = lane & 15;           // column within block
    const int chunk = 2 * w0 + h;          // 32-row chunk 0..31
    const long long gcol = (long long)blockIdx.x * COLS + c16;

    u64 Xp[16];                            // layout A: u64 k = rows (32*chunk+k, +16)

    // ---- load (two coalesced 64B half-warp segments per k) ----
#pragma unroll
    for (int k = 0; k < 16; ++k) {
        const float lo = __ldcg(X + (long long)(32 * chunk + k)      * BATCH + gcol);
        const float hi = __ldcg(X + (long long)(32 * chunk + k + 16) * BATCH + gcol);
        Xp[k] = pk(lo, hi);
    }

#pragma unroll 1
    for (int p = 0; p < 2; ++p) {
        const ulonglong2* tN = g_tabN + (p * 8) * 256 + chunk * 8;
        const ulonglong2* tS = g_tabS + (p * 2) * 512 + chunk * 16;

        // layers p*10 + 0..4 : strides 1,2,4,8 normal + 16 swap (layout A)
        lnorm<0>(Xp, tN + 0 * 256);
        lnorm<1>(Xp, tN + 1 * 256);
        lnorm<2>(Xp, tN + 2 * 256);
        lnorm<3>(Xp, tN + 3 * 256);
        lswap(Xp, tS);

        // ---- exchange A -> B ----
        __syncthreads();
#pragma unroll
        for (int k = 0; k < 16; ++k) {
            float lo, hi; up(Xp[k], lo, hi);
            tile[tadr(32 * chunk + k,      c16)] = lo;
            tile[tadr(32 * chunk + k + 16, c16)] = hi;
        }
        __syncthreads();
#pragma unroll
        for (int i = 0; i < 16; ++i) {
            const float lo = tile[tadr(chunk + 32 * i,       c16)];
            const float hi = tile[tadr(chunk + 32 * i + 512, c16)];
            Xp[i] = pk(lo, hi);            // layout B: u64 i = rows (chunk+32i, +512)
        }

        // layers p*10 + 5..9 : strides 32,64,128,256 normal + 512 swap (layout B)
        lnorm<0>(Xp, tN + 4 * 256);
        lnorm<1>(Xp, tN + 5 * 256);
        lnorm<2>(Xp, tN + 6 * 256);
        lnorm<3>(Xp, tN + 7 * 256);
        lswap(Xp, tS + 512);

        if (p == 0) {
            // ---- exchange B -> A ----
            __syncthreads();
#pragma unroll
            for (int i = 0; i < 16; ++i) {
                float lo, hi; up(Xp[i], lo, hi);
                tile[tadr(chunk + 32 * i,       c16)] = lo;
                tile[tadr(chunk + 32 * i + 512, c16)] = hi;
            }
            __syncthreads();
#pragma unroll
            for (int k = 0; k < 16; ++k) {
                const float lo = tile[tadr(32 * chunk + k,      c16)];
                const float hi = tile[tadr(32 * chunk + k + 16, c16)];
                Xp[k] = pk(lo, hi);
            }
        }
    }

    // ---- store from layout B ----
#pragma unroll
    for (int i = 0; i < 16; ++i) {
        float lo, hi; up(Xp[i], lo, hi);
        __stcg(Y + (long long)(chunk + 32 * i)       * BATCH + gcol, lo);
        __stcg(Y + (long long)(chunk + 32 * i + 512) * BATCH + gcol, hi);
    }
}

extern "C" void kernel_launch(void* const* d_in, const int* in_sizes, int n_in,
                              void* d_out, int out_size)
{
    const float* X = (const float*)d_in[0];
    const float* A = (const float*)d_in[1];
    if (n_in >= 2 && in_sizes[0] < in_sizes[1]) {   // defensive: X is the big one
        const float* t = X; X = A; A = t;
    }
    float* Y = (float*)d_out;

    cudaFuncSetAttribute(butterfly_kernel,
                         cudaFuncAttributeMaxDynamicSharedMemorySize, 65536);

    prep_kernel<<<(6144 + 255) / 256, 256>>>(A);
    butterfly_kernel<<<NBLOCKS, NTHREADS, 65536>>>(X, Y);
}

// round 10
// speedup vs baseline: 1.6649x; 1.6649x over previous
#include <cuda_runtime.h>

typedef unsigned long long u64;

#define HALF     512
#define BATCH    8192
#define DEPTH    20
#define TB       16          // batch columns per block (4 bq threads x 4 cols)
#define NTHREADS 128         // 32 row-threads x 4 batch-quad threads
#define NBLOCKS  (BATCH / TB)

// Scalar (c, s) coefficients, 8B each. P1-type layers (l%10 < 5) stored
// PERMUTED: natural pair index p -> slot (p&15)*32 + (p>>4), so BOTH pass
// types address coefs as m*32 + rt; a warp's 8 consecutive rt values read
// 64 consecutive bytes (1 sector), broadcast across the 4 bq lanes.
__device__ float2 g_cs[DEPTH * HALF];

__global__ void sincos_kernel(const float* __restrict__ ang) {
    int i = blockIdx.x * blockDim.x + threadIdx.x;
    if (i < DEPTH * HALF) {
        const int l = i / HALF;
        const int p = i % HALF;
        float s, c;
        sincosf(ang[i], &s, &c);
        const int slot = ((l % 10) < 5) ? ((p & 15) * 32 + (p >> 4)) : p;
        g_cs[l * HALF + slot] = make_float2(c, s);
    }
}

// ---- packed f32x2 helpers (sm_100) ----
__device__ __forceinline__ u64 pk2(float v) {
    u64 r; asm("mov.b64 %0, {%1, %1};" : "=l"(r) : "f"(v)); return r;
}
__device__ __forceinline__ u64 mul2(u64 a, u64 b) {
    u64 d; asm("mul.rn.f32x2 %0, %1, %2;" : "=l"(d) : "l"(a), "l"(b)); return d;
}
__device__ __forceinline__ u64 fma2(u64 a, u64 b, u64 c) {
    u64 d; asm("fma.rn.f32x2 %0, %1, %2, %3;" : "=l"(d) : "l"(a), "l"(b), "l"(c)); return d;
}

// Givens rotation on one packed pair: y0 = c*x0 + s*x1 ; y1 = -s*x0 + c*x1
__device__ __forceinline__ void rot(u64& x0, u64& x1, u64 cc, u64 ss, u64 ns) {
    const u64 y0 = fma2(cc, x0, mul2(ss, x1));
    const u64 y1 = fma2(ns, x0, mul2(cc, x1));
    x0 = y0; x1 = y1;
}

// Five butterfly levels fully in registers on 4 batch columns (Xa, Xb = 2
// packed pairs -> 4 independent FMA chains per rotation). Flattened into 20
// q-steps with a dist-1 pipelined coefficient stream.
// Coef slot = m*32 + rt; pairs (j, j+2^l), j = ((m>>l)<<(l+1)) | (m & (2^l-1)).
__device__ __forceinline__ void pass5(u64* Xa, u64* Xb, const float2* __restrict__ lt) {
    float2 cf[4];
#pragma unroll
    for (int t = 0; t < 4; ++t) cf[t] = __ldg(lt + t * 32);

#pragma unroll
    for (int u = 0; u < 20; ++u) {
        const int l = u >> 2;
        const int q = u & 3;
        float2 nf[4];
        if (u < 19) {
            const int l2 = (u + 1) >> 2;
            const int q2 = (u + 1) & 3;
#pragma unroll
            for (int t = 0; t < 4; ++t)
                nf[t] = __ldg(lt + l2 * HALF + (q2 * 4 + t) * 32);
        }
#pragma unroll
        for (int t = 0; t < 4; ++t) {
            const int m  = q * 4 + t;
            const int sg = 1 << l;
            const int j  = ((m >> l) << (l + 1)) | (m & (sg - 1));
            const u64 cc = pk2(cf[t].x);
            const u64 ss = pk2(cf[t].y);
            const u64 ns = ss ^ 0x8000000080000000ULL;
            rot(Xa[j], Xa[j + sg], cc, ss, ns);
            rot(Xb[j], Xb[j + sg], cc, ss, ns);
        }
#pragma unroll
        for (int t = 0; t < 4; ++t) cf[t] = nf[t];
    }
}

// Smem swizzle in 16B units (hardware-verified in R5):
// addr(row,bq) = ((row ^ ((row>>5)&1)) << 2) | bq. For warp = 8 rt x 4 bq,
// both exchange groupings hit each 128B bank-group with exactly 4 lanes ->
// 512B warp accesses at the 4-phase minimum. Bijective.
#define ADRA(j) (baseA + (((j) ^ eA) << 2))                 // row = rt*32+j
#define ADRB(j) ((j) * 128 + (((j) & 1) ? baseB1 : baseB0)) // row = rt+32j

extern "C" __global__ void __launch_bounds__(NTHREADS, 2)
butterfly_kernel(const float* __restrict__ X, float* __restrict__ Y)
{
    extern __shared__ ulonglong2 tile[];   // 1024 rows x 4 bq x 16B = 64 KB

    const int bq = threadIdx.x & 3;        // batch-quad (4 cols) 0..3
    const int rt = threadIdx.x >> 2;       // row-thread 0..31
    const long long bb = (long long)blockIdx.x * TB + bq * 4;

    const int eA     = rt & 1;
    const int baseA  = rt * 128 + bq;
    const int baseB0 = (rt << 2) + bq;
    const int baseB1 = ((rt ^ 1) << 2) + bq;

    u64 Xa[32], Xb[32];                    // 32 rows x 4 batch columns

    // Load, layout A (reg j = row rt*32+j); .cg keeps L1 for the coef table.
#pragma unroll
    for (int j = 0; j < 32; ++j) {
        const float4 v = __ldcg(
            reinterpret_cast<const float4*>(X + (long long)(rt * 32 + j) * BATCH + bb));
        asm("mov.b64 %0, {%2, %3}; mov.b64 %1, {%4, %5};"
            : "=l"(Xa[j]), "=l"(Xb[j]) : "f"(v.x), "f"(v.y), "f"(v.z), "f"(v.w));
    }

    const float2* lt = g_cs + rt;

#pragma unroll 1
    for (int sp = 0; sp < 2; ++sp) {
        // layers sp*10 .. sp*10+4 (register strides 1..16 in layout A)
        pass5(Xa, Xb, lt + (sp * 10) * HALF);

        // exchange A -> B
        __syncthreads();
#pragma unroll
        for (int j = 0; j < 32; ++j) tile[ADRA(j)] = make_ulonglong2(Xa[j], Xb[j]);
        __syncthreads();
#pragma unroll
        for (int j = 0; j < 32; ++j) {
            const ulonglong2 v = tile[ADRB(j)];
            Xa[j] = v.x; Xb[j] = v.y;
        }

        // layers sp*10+5 .. sp*10+9 (strides 32..512 in layout B)
        pass5(Xa, Xb, lt + (sp * 10 + 5) * HALF);

        if (sp == 0) {
            // exchange B -> A
            __syncthreads();
#pragma unroll
            for (int j = 0; j < 32; ++j) tile[ADRB(j)] = make_ulonglong2(Xa[j], Xb[j]);
            __syncthreads();
#pragma unroll
            for (int j = 0; j < 32; ++j) {
                const ulonglong2 v = tile[ADRA(j)];
                Xa[j] = v.x; Xb[j] = v.y;
            }
        }
    }

    // Store, layout B (reg j = row rt+32j), .cg to bypass L1.
#pragma unroll
    for (int j = 0; j < 32; ++j) {
        float x, y, z, w;
        asm("mov.b64 {%0, %1}, %4; mov.b64 {%2, %3}, %5;"
            : "=f"(x), "=f"(y), "=f"(z), "=f"(w) : "l"(Xa[j]), "l"(Xb[j]));
        __stcg(reinterpret_cast<float4*>(Y + (long long)(rt + 32 * j) * BATCH + bb),
               make_float4(x, y, z, w));
    }
}

extern "C" void kernel_launch(void* const* d_in, const int* in_sizes, int n_in,
                              void* d_out, int out_size)
{
    const float* X = (const float*)d_in[0];
    const float* A = (const float*)d_in[1];
    if (n_in >= 2 && in_sizes[0] < in_sizes[1]) {   // defensive: X is the big one
        const float* t = X; X = A; A = t;
    }
    float* Y = (float*)d_out;

    cudaFuncSetAttribute(butterfly_kernel,
                         cudaFuncAttributeMaxDynamicSharedMemorySize, 65536);

    sincos_kernel<<<(DEPTH * HALF + 255) / 256, 256>>>(A);
    butterfly_kernel<<<NBLOCKS, NTHREADS, 65536>>>(X, Y);
}